// round 10
// baseline (speedup 1.0000x reference)
#include <cuda_runtime.h>
#include <math.h>

#define T_ALL 128
#define T_STEPS 127
#define BSZ 256
#define DD 512
#define HH 1024
#define OO 20
#define KC 320                     // Eigen gebp kc panel boundary (confirmed R5)
#define TCHUNK 16                  // timesteps per in_gemm chunk
#define NCHUNK 8

__device__ __constant__ float c_ALPHA = 0.95122942450071400909f; // fp32(exp(-1/20))
__device__ __constant__ float c_KAPPA = 0.95122942450071400909f;
#define THRv 1.0f

// ---- scratch (device globals; no allocation allowed) ----
__device__ float g_xin[(size_t)T_STEPS * BSZ * HH];   // 133 MB
__device__ float g_WT[HH * HH];        // WT[j][h] = w_rec_eff[h][j] (diag zeroed)
__device__ int   g_ready;              // chunk-completion flag
__device__ int   g_cnt8[NCHUNK];       // per-chunk block counters

// packed dual fp32 FMA (per-lane IEEE rn — bit-exact per chain)
#define FMA2(d_, a_, b_) \
    asm("fma.rn.f32x2 %0, %1, %2, %3;" : "=l"(d_) : "l"(a_), "l"(b_), "l"(d_))

__device__ __forceinline__ float2 unpack2(unsigned long long u) {
    float2 f;
    asm("mov.b64 {%0, %1}, %2;" : "=f"(f.x), "=f"(f.y) : "l"(u));
    return f;
}

// ============================================================
__global__ void reset_k() {
    g_ready = 0;
#pragma unroll
    for (int i = 0; i < NCHUNK; i++) g_cnt8[i] = 0;
}

// ============================================================
// prep: transposed, diagonal-zeroed recurrent weights
// ============================================================
__global__ void __launch_bounds__(256) prep_k(const float* __restrict__ w_rec) {
    int idx = blockIdx.x * 256 + threadIdx.x;
    int stride = gridDim.x * 256;
    for (int i = idx; i < HH * HH; i += stride) {
        int j = i / HH, h = i % HH;
        g_WT[i] = (h == j) ? 0.0f : w_rec[(size_t)h * HH + j];
    }
}

// ============================================================
// input GEMM chunk (bit-exact ascending-k chain, kc=320 fold):
// 128m x 64n tile, BK=8 double-buffered, 256 threads, 8x4 microtile
// via fma.rn.f32x2; low-reg so >=2 blocks/SM co-resident with step_all
// ============================================================
__global__ void __launch_bounds__(256, 2) in_gemm(const float* __restrict__ x,
                                                  const float* __restrict__ w_in,
                                                  int m_base, int chunk, int nblocks) {
    __shared__ float As2[2][8][256];    // duplicated pairs: As2[d][2m]=As2[d][2m+1]
    __shared__ float Bs[2][8][64];
    const int tid = threadIdx.x;
    const int m0 = m_base + blockIdx.y * 128;
    const int n0 = blockIdx.x * 64;

    const int lr  = tid >> 1;           // 0..127 A row
    const int lk  = (tid & 1) * 4;      // 0/4
    const int lrB = tid >> 2;           // 0..63 B row
    const int lkB = (tid & 3) * 2;      // 0,2,4,6
    const int tm  = (tid >> 4) * 8;     // 0..120
    const int tn  = (tid & 15) * 4;     // 0..60

    const float* Ap = x + (size_t)(m0 + lr) * DD + lk;
    const float* Bp = w_in + (size_t)(n0 + lrB) * DD + lkB;

    float4 a  = __ldcs((const float4*)Ap);
    float2 bb = *(const float2*)Bp;
    *(float2*)&As2[0][lk + 0][2 * lr] = make_float2(a.x, a.x);
    *(float2*)&As2[0][lk + 1][2 * lr] = make_float2(a.y, a.y);
    *(float2*)&As2[0][lk + 2][2 * lr] = make_float2(a.z, a.z);
    *(float2*)&As2[0][lk + 3][2 * lr] = make_float2(a.w, a.w);
    Bs[0][lkB + 0][lrB] = bb.x;
    Bs[0][lkB + 1][lrB] = bb.y;
    __syncthreads();

    unsigned long long acc2[8][2];      // [m][jpair]: cols (tn+2jp, tn+2jp+1)
#pragma unroll
    for (int i = 0; i < 8; i++) { acc2[i][0] = 0ULL; acc2[i][1] = 0ULL; }

    int s = 0;
    for (int k0 = 0; k0 < DD; k0 += 8) {
        const int nk = k0 + 8;
        if (nk < DD) {
            a  = __ldcs((const float4*)(Ap + nk));
            bb = *(const float2*)(Bp + nk);
        }
#pragma unroll
        for (int d = 0; d < 8; d++) {   // ascending k
            ulonglong2 ar01 = *(const ulonglong2*)(&As2[s][d][2 * tm + 0]);
            ulonglong2 ar23 = *(const ulonglong2*)(&As2[s][d][2 * tm + 4]);
            ulonglong2 ar45 = *(const ulonglong2*)(&As2[s][d][2 * tm + 8]);
            ulonglong2 ar67 = *(const ulonglong2*)(&As2[s][d][2 * tm + 12]);
            ulonglong2 br   = *(const ulonglong2*)(&Bs[s][d][tn]);
            unsigned long long ar[8] = {ar01.x, ar01.y, ar23.x, ar23.y,
                                        ar45.x, ar45.y, ar67.x, ar67.y};
#pragma unroll
            for (int i = 0; i < 8; i++) {
                FMA2(acc2[i][0], ar[i], br.x);
                FMA2(acc2[i][1], ar[i], br.y);
            }
        }
        if (nk == KC) {                 // stage panel 0 to global, restart chain
#pragma unroll
            for (int i = 0; i < 8; i++) {
                float* dst = g_xin + (size_t)(m0 + tm + i) * HH + n0 + tn;
                float2 u0 = unpack2(acc2[i][0]), u1 = unpack2(acc2[i][1]);
                *(float4*)dst = make_float4(u0.x, u0.y, u1.x, u1.y);
                acc2[i][0] = 0ULL; acc2[i][1] = 0ULL;
            }
        }
        if (nk < DD) {
            *(float2*)&As2[s ^ 1][lk + 0][2 * lr] = make_float2(a.x, a.x);
            *(float2*)&As2[s ^ 1][lk + 1][2 * lr] = make_float2(a.y, a.y);
            *(float2*)&As2[s ^ 1][lk + 2][2 * lr] = make_float2(a.z, a.z);
            *(float2*)&As2[s ^ 1][lk + 3][2 * lr] = make_float2(a.w, a.w);
            Bs[s ^ 1][lkB + 0][lrB] = bb.x;
            Bs[s ^ 1][lkB + 1][lrB] = bb.y;
        }
        __syncthreads();
        s ^= 1;
    }

    // fold: xin = fadd(p0, p1)  (exact Eigen panel fold)
#pragma unroll
    for (int i = 0; i < 8; i++) {
        float* dst = g_xin + (size_t)(m0 + tm + i) * HH + n0 + tn;
        float4 p0 = *(const float4*)dst;
        float2 u0 = unpack2(acc2[i][0]), u1 = unpack2(acc2[i][1]);
        float4 o;
        o.x = __fadd_rn(p0.x, u0.x); o.y = __fadd_rn(p0.y, u0.y);
        o.z = __fadd_rn(p0.z, u1.x); o.w = __fadd_rn(p0.w, u1.y);
        __stcs((float4*)dst, o);
    }

    // chunk-completion signal (replaces marker kernels)
    __threadfence();
    __syncthreads();
    if (tid == 0) {
        int v = atomicAdd(&g_cnt8[chunk], 1);
        if (v == nblocks - 1) atomicExch(&g_ready, chunk + 1);
    }
}

// ============================================================
// persistent per-batch-row kernel: block b runs ALL 127 steps,
// then softmaxes its 128 output rows. Bit-exact v-path.
// ============================================================
__global__ void __launch_bounds__(256) step_all(const float* __restrict__ w_out,
                                                float* __restrict__ out) {
    const int b = blockIdx.x;
    const int tid = threadIdx.x;
    const int lane = tid & 31, wid = tid >> 5;
    const int h4 = tid * 4;

    __shared__ int lists[2][HH];
    __shared__ int s_po[5];
    __shared__ int s_wsum[8], s_woff[8];
    __shared__ int s_total;
    __shared__ float s_red[OO][9];

    float v0 = 0.f, v1 = 0.f, v2 = 0.f, v3 = 0.f;
    float vo = 0.f;

    if (tid < 5) s_po[tid] = 0;
    if (tid < OO) out[(size_t)b * OO + tid] = 0.f;   // row t=0
    __syncthreads();

    for (int t = 0; t < T_STEPS; t++) {
        if ((t & (TCHUNK - 1)) == 0) {
            if (tid == 0) {
                const int need = (t >> 4) + 1;
                while (*((volatile int*)&g_ready) < need) __nanosleep(200);
                __threadfence();                      // acquire ordering for xin
            }
            __syncthreads();
        }

        const int* act = lists[t & 1];
        int* nxt = lists[(t + 1) & 1];

        // ---- sparse recurrent sum: exact per-panel chains, MLP-8 ----
        float tot0 = 0.f, tot1 = 0.f, tot2 = 0.f, tot3 = 0.f;
#pragma unroll 1
        for (int p = 0; p < 4; p++) {
            const int beg = s_po[p], end = s_po[p + 1];
            float a0 = 0.f, a1 = 0.f, a2 = 0.f, a3 = 0.f;
            int i = beg;
            for (; i + 8 <= end; i += 8) {
                float4 w[8];
#pragma unroll
                for (int q = 0; q < 8; q++)
                    w[q] = *(const float4*)(g_WT + (size_t)act[i + q] * HH + h4);
#pragma unroll
                for (int q = 0; q < 8; q++) {
                    a0 = __fadd_rn(a0, w[q].x);
                    a1 = __fadd_rn(a1, w[q].y);
                    a2 = __fadd_rn(a2, w[q].z);
                    a3 = __fadd_rn(a3, w[q].w);
                }
            }
            for (; i < end; i++) {
                const float4 w = *(const float4*)(g_WT + (size_t)act[i] * HH + h4);
                a0 = __fadd_rn(a0, w.x);
                a1 = __fadd_rn(a1, w.y);
                a2 = __fadd_rn(a2, w.z);
                a3 = __fadd_rn(a3, w.w);
            }
            tot0 = __fadd_rn(tot0, a0);
            tot1 = __fadd_rn(tot1, a1);
            tot2 = __fadd_rn(tot2, a2);
            tot3 = __fadd_rn(tot3, a3);
        }

        // ---- v update ----
        const float4 xi = __ldcs((const float4*)(g_xin + (size_t)t * BSZ * HH
                                                 + (size_t)b * HH + h4));
        const float zp0 = (v0 > THRv) ? 1.f : 0.f;
        const float zp1 = (v1 > THRv) ? 1.f : 0.f;
        const float zp2 = (v2 > THRv) ? 1.f : 0.f;
        const float zp3 = (v3 > THRv) ? 1.f : 0.f;

        v0 = __fsub_rn(__fadd_rn(__fmaf_rn(c_ALPHA, v0, tot0), xi.x), zp0);
        v1 = __fsub_rn(__fadd_rn(__fmaf_rn(c_ALPHA, v1, tot1), xi.y), zp1);
        v2 = __fsub_rn(__fadd_rn(__fmaf_rn(c_ALPHA, v2, tot2), xi.z), zp2);
        v3 = __fsub_rn(__fadd_rn(__fmaf_rn(c_ALPHA, v3, tot3), xi.w), zp3);

        const bool z0 = v0 > THRv, z1 = v1 > THRv, z2 = v2 > THRv, z3 = v3 > THRv;
        const int cnt = (int)z0 + (int)z1 + (int)z2 + (int)z3;

        // ---- ordered block scan -> ascending active list for t+1 ----
        int s = cnt;
#pragma unroll
        for (int o = 1; o < 32; o <<= 1) {
            int u = __shfl_up_sync(0xffffffffu, s, o);
            if (lane >= o) s += u;
        }
        if (lane == 31) s_wsum[wid] = s;
        __syncthreads();
        if (wid == 0 && lane < 8) {
            int u = s_wsum[lane];
            int sc = u;
#pragma unroll
            for (int o = 1; o < 8; o <<= 1) {
                int q = __shfl_up_sync(0xffu, sc, o);
                if (lane >= o) sc += q;
            }
            s_woff[lane] = sc - u;
            if (lane == 7) s_total = sc;
        }
        __syncthreads();

        int o = s_woff[wid] + s - cnt;
        if (z0) nxt[o++] = h4 + 0;
        if (z1) nxt[o++] = h4 + 1;
        if (z2) nxt[o++] = h4 + 2;
        if (z3) nxt[o++] = h4 + 3;

        const int incl = s_woff[wid] + s;
        if (tid == 79)  s_po[1] = incl;       // h < 320
        if (tid == 159) s_po[2] = incl;       // h < 640
        if (tid == 239) s_po[3] = incl;       // h < 960
        if (tid == 255) { s_po[4] = incl; s_po[0] = 0; }
        __syncthreads();

        // ---- output projection over new spikes (order-free) ----
        const int total = s_total;
        if (tid < OO * 8) {
            const int oo = tid >> 3, c = tid & 7;
            const float* wr = w_out + (size_t)oo * HH;
            float acc = 0.f;
            for (int i = c; i < total; i += 8)
                acc += wr[nxt[i]];
            s_red[oo][c] = acc;
        }
        __syncthreads();
        if (tid < OO) {
            float ssum = s_red[tid][0];
#pragma unroll
            for (int c = 1; c < 8; c++) ssum += s_red[tid][c];
            vo = __fmaf_rn(c_KAPPA, vo, ssum);
            out[((size_t)(t + 1) * BSZ + b) * OO + tid] = vo;
        }
        __syncthreads();
    }

    // ---- softmax of this b's 128 rows (warp per row) ----
    __syncthreads();
    for (int r = wid; r < T_ALL; r += 8) {
        float* pr = out + ((size_t)r * BSZ + b) * OO;
        float vv = (lane < OO) ? pr[lane] : -INFINITY;
        float m = vv;
#pragma unroll
        for (int off = 16; off > 0; off >>= 1)
            m = fmaxf(m, __shfl_xor_sync(0xffffffff, m, off));
        float e = (lane < OO) ? expf(vv - m) : 0.f;
        float sm = e;
#pragma unroll
        for (int off = 16; off > 0; off >>= 1)
            sm += __shfl_xor_sync(0xffffffff, sm, off);
        if (lane < OO) pr[lane] = e / sm;
    }
}

// ============================================================
extern "C" void kernel_launch(void* const* d_in, const int* in_sizes, int n_in,
                              void* d_out, int out_size) {
    const float* x     = (const float*)d_in[0];  // [128,256,512]
    const float* w_in  = (const float*)d_in[1];  // [1024,512]
    const float* w_rec = (const float*)d_in[2];  // [1024,1024]
    const float* w_out = (const float*)d_in[3];  // [20,1024]
    float* out = (float*)d_out;                  // [128,256,20]

    static cudaStream_t s2 = nullptr;
    static cudaEvent_t eF = nullptr, eJ = nullptr;
    if (!s2) {
        cudaStreamCreateWithFlags(&s2, cudaStreamNonBlocking);
        cudaEventCreateWithFlags(&eF, cudaEventDisableTiming);
        cudaEventCreateWithFlags(&eJ, cudaEventDisableTiming);
    }

    reset_k<<<1, 1>>>();                         // reset flag + counters

    // fork: prep + input-GEMM chunks on side stream
    cudaEventRecord(eF, 0);
    cudaStreamWaitEvent(s2, eF, 0);
    prep_k<<<512, 256, 0, s2>>>(w_rec);
    for (int c = 0; c < NCHUNK; c++) {
        const int tcnt = (c == NCHUNK - 1) ? (T_STEPS - (NCHUNK - 1) * TCHUNK) : TCHUNK;
        const int yblocks = (tcnt * BSZ) / 128;
        const int nblocks = (HH / 64) * yblocks;
        in_gemm<<<dim3(HH / 64, yblocks), 256, 0, s2>>>(x, w_in,
                                                        c * TCHUNK * BSZ, c, nblocks);
    }
    cudaEventRecord(eJ, s2);

    // persistent recurrent scan (overlaps with in_gemm via flag gating)
    step_all<<<BSZ, 256>>>(w_out, out);

    cudaStreamWaitEvent(0, eJ, 0);               // join side stream into capture
}

// round 11
// speedup vs baseline: 1.0505x; 1.0505x over previous
#include <cuda_runtime.h>
#include <math.h>

#define T_ALL 128
#define T_STEPS 127
#define BSZ 256
#define DD 512
#define HH 1024
#define OO 20
#define KC 320                     // Eigen gebp kc panel boundary (confirmed R5)

__device__ __constant__ float c_ALPHA = 0.95122942450071400909f; // fp32(exp(-1/20))
__device__ __constant__ float c_KAPPA = 0.95122942450071400909f;
#define THRv 1.0f

// ---- scratch (device globals; no allocation allowed) ----
__device__ float g_xin[(size_t)T_STEPS * BSZ * HH];   // 133 MB
__device__ float g_WT[HH * HH];        // WT[j][h] = w_rec_eff[h][j] (diag zeroed)

// packed dual fp32 FMA (per-lane IEEE rn — bit-exact per chain)
#define FMA2(d_, a_, b_) \
    asm("fma.rn.f32x2 %0, %1, %2, %3;" : "=l"(d_) : "l"(a_), "l"(b_), "l"(d_))

__device__ __forceinline__ float2 unpack2(unsigned long long u) {
    float2 f;
    asm("mov.b64 {%0, %1}, %2;" : "=f"(f.x), "=f"(f.y) : "l"(u));
    return f;
}

// ============================================================
// prep: transposed, diagonal-zeroed recurrent weights
// ============================================================
__global__ void __launch_bounds__(256) prep_k(const float* __restrict__ w_rec) {
    int idx = blockIdx.x * 256 + threadIdx.x;
    int stride = gridDim.x * 256;
    for (int i = idx; i < HH * HH; i += stride) {
        int j = i / HH, h = i % HH;
        g_WT[i] = (h == j) ? 0.0f : w_rec[(size_t)h * HH + j];
    }
}

// ============================================================
// input GEMM (bit-exact ascending-k chain, kc=320 fold):
// 128m x 64n tile, BK=8 double-buffered, 256 threads, 8x4 microtile
// fma.rn.f32x2 packed over m-PAIRS: A tile natural layout (consecutive
// m = ready pairs), B tile duplicated. 4 LDS.128 per 32 MACs per d.
// grid (16, 254)
// ============================================================
__global__ void __launch_bounds__(256) in_gemm(const float* __restrict__ x,
                                               const float* __restrict__ w_in) {
    __shared__ float As[2][8][128];     // [k][m], natural
    __shared__ float Bs2[2][8][128];    // [k][2n] duplicated pairs
    const int tid = threadIdx.x;
    const int m0 = blockIdx.y * 128;
    const int n0 = blockIdx.x * 64;

    const int lr  = tid >> 1;           // 0..127 A row
    const int lk  = (tid & 1) * 4;      // 0/4
    const int lrB = tid >> 2;           // 0..63 B row
    const int lkB = (tid & 3) * 2;      // 0,2,4,6
    const int tm  = (tid >> 4) * 8;     // 0..120  (4 m-pairs)
    const int tn  = (tid & 15) * 4;     // 0..60   (4 n cols)

    const float* Ap = x + (size_t)(m0 + lr) * DD + lk;
    const float* Bp = w_in + (size_t)(n0 + lrB) * DD + lkB;

    float4 a  = __ldcs((const float4*)Ap);
    float2 bb = *(const float2*)Bp;
    As[0][lk + 0][lr] = a.x; As[0][lk + 1][lr] = a.y;
    As[0][lk + 2][lr] = a.z; As[0][lk + 3][lr] = a.w;
    *(float2*)&Bs2[0][lkB + 0][2 * lrB] = make_float2(bb.x, bb.x);
    *(float2*)&Bs2[0][lkB + 1][2 * lrB] = make_float2(bb.y, bb.y);
    __syncthreads();

    // acc2[ip][j]: lanes = rows (tm+2ip, tm+2ip+1), column tn+j
    unsigned long long acc2[4][4];
#pragma unroll
    for (int i = 0; i < 4; i++)
#pragma unroll
        for (int j = 0; j < 4; j++) acc2[i][j] = 0ULL;

    int s = 0;
    for (int k0 = 0; k0 < DD; k0 += 8) {
        const int nk = k0 + 8;
        if (nk < DD) {                  // prefetch next k-tile
            a  = __ldcs((const float4*)(Ap + nk));
            bb = *(const float2*)(Bp + nk);
        }
#pragma unroll
        for (int d = 0; d < 8; d++) {   // ascending k
            ulonglong2 ar01 = *(const ulonglong2*)(&As[s][d][tm + 0]);   // pairs (m0,m1),(m2,m3)
            ulonglong2 ar23 = *(const ulonglong2*)(&As[s][d][tm + 4]);   // pairs (m4,m5),(m6,m7)
            ulonglong2 br01 = *(const ulonglong2*)(&Bs2[s][d][2 * tn + 0]); // dup(n0), dup(n1)
            ulonglong2 br23 = *(const ulonglong2*)(&Bs2[s][d][2 * tn + 4]); // dup(n2), dup(n3)
            unsigned long long ar[4] = {ar01.x, ar01.y, ar23.x, ar23.y};
            unsigned long long br[4] = {br01.x, br01.y, br23.x, br23.y};
#pragma unroll
            for (int i = 0; i < 4; i++)
#pragma unroll
                for (int j = 0; j < 4; j++)
                    FMA2(acc2[i][j], ar[i], br[j]);
        }
        if (nk == KC) {                 // stage panel 0 to global, restart chain
#pragma unroll
            for (int i = 0; i < 4; i++) {
                float2 u0 = unpack2(acc2[i][0]), u1 = unpack2(acc2[i][1]);
                float2 u2 = unpack2(acc2[i][2]), u3 = unpack2(acc2[i][3]);
                float* d0 = g_xin + (size_t)(m0 + tm + 2 * i + 0) * HH + n0 + tn;
                float* d1 = g_xin + (size_t)(m0 + tm + 2 * i + 1) * HH + n0 + tn;
                *(float4*)d0 = make_float4(u0.x, u1.x, u2.x, u3.x);
                *(float4*)d1 = make_float4(u0.y, u1.y, u2.y, u3.y);
#pragma unroll
                for (int j = 0; j < 4; j++) acc2[i][j] = 0ULL;
            }
        }
        if (nk < DD) {
            As[s ^ 1][lk + 0][lr] = a.x; As[s ^ 1][lk + 1][lr] = a.y;
            As[s ^ 1][lk + 2][lr] = a.z; As[s ^ 1][lk + 3][lr] = a.w;
            *(float2*)&Bs2[s ^ 1][lkB + 0][2 * lrB] = make_float2(bb.x, bb.x);
            *(float2*)&Bs2[s ^ 1][lkB + 1][2 * lrB] = make_float2(bb.y, bb.y);
        }
        __syncthreads();
        s ^= 1;
    }

    // fold: xin = fadd(p0, p1)  (exact Eigen panel fold)
#pragma unroll
    for (int i = 0; i < 4; i++) {
        float2 u0 = unpack2(acc2[i][0]), u1 = unpack2(acc2[i][1]);
        float2 u2 = unpack2(acc2[i][2]), u3 = unpack2(acc2[i][3]);
        float* d0 = g_xin + (size_t)(m0 + tm + 2 * i + 0) * HH + n0 + tn;
        float* d1 = g_xin + (size_t)(m0 + tm + 2 * i + 1) * HH + n0 + tn;
        float4 p0 = *(const float4*)d0;
        float4 p1 = *(const float4*)d1;
        float4 o0, o1;
        o0.x = __fadd_rn(p0.x, u0.x); o0.y = __fadd_rn(p0.y, u1.x);
        o0.z = __fadd_rn(p0.z, u2.x); o0.w = __fadd_rn(p0.w, u3.x);
        o1.x = __fadd_rn(p1.x, u0.y); o1.y = __fadd_rn(p1.y, u1.y);
        o1.z = __fadd_rn(p1.z, u2.y); o1.w = __fadd_rn(p1.w, u3.y);
        __stcs((float4*)d0, o0);
        __stcs((float4*)d1, o1);
    }
}

// ============================================================
// persistent per-batch-row kernel: block b runs ALL 127 steps,
// then softmaxes its 128 output rows. Bit-exact v-path.
// ============================================================
__global__ void __launch_bounds__(256) step_all(const float* __restrict__ w_out,
                                                float* __restrict__ out) {
    const int b = blockIdx.x;
    const int tid = threadIdx.x;
    const int lane = tid & 31, wid = tid >> 5;
    const int h4 = tid * 4;

    __shared__ int lists[2][HH];
    __shared__ int s_po[5];
    __shared__ int s_wsum[8], s_woff[8];
    __shared__ int s_total;
    __shared__ float s_red[OO][9];

    float v0 = 0.f, v1 = 0.f, v2 = 0.f, v3 = 0.f;
    float vo = 0.f;

    if (tid < 5) s_po[tid] = 0;
    if (tid < OO) out[(size_t)b * OO + tid] = 0.f;   // row t=0
    __syncthreads();

    for (int t = 0; t < T_STEPS; t++) {
        const int* act = lists[t & 1];
        int* nxt = lists[(t + 1) & 1];

        // ---- sparse recurrent sum: exact per-panel chains, MLP-8 ----
        float tot0 = 0.f, tot1 = 0.f, tot2 = 0.f, tot3 = 0.f;
#pragma unroll 1
        for (int p = 0; p < 4; p++) {
            const int beg = s_po[p], end = s_po[p + 1];
            float a0 = 0.f, a1 = 0.f, a2 = 0.f, a3 = 0.f;
            int i = beg;
            for (; i + 8 <= end; i += 8) {
                float4 w[8];
#pragma unroll
                for (int q = 0; q < 8; q++)
                    w[q] = *(const float4*)(g_WT + (size_t)act[i + q] * HH + h4);
#pragma unroll
                for (int q = 0; q < 8; q++) {
                    a0 = __fadd_rn(a0, w[q].x);
                    a1 = __fadd_rn(a1, w[q].y);
                    a2 = __fadd_rn(a2, w[q].z);
                    a3 = __fadd_rn(a3, w[q].w);
                }
            }
            for (; i < end; i++) {
                const float4 w = *(const float4*)(g_WT + (size_t)act[i] * HH + h4);
                a0 = __fadd_rn(a0, w.x);
                a1 = __fadd_rn(a1, w.y);
                a2 = __fadd_rn(a2, w.z);
                a3 = __fadd_rn(a3, w.w);
            }
            tot0 = __fadd_rn(tot0, a0);
            tot1 = __fadd_rn(tot1, a1);
            tot2 = __fadd_rn(tot2, a2);
            tot3 = __fadd_rn(tot3, a3);
        }

        // ---- v update ----
        const float4 xi = __ldcs((const float4*)(g_xin + (size_t)t * BSZ * HH
                                                 + (size_t)b * HH + h4));
        const float zp0 = (v0 > THRv) ? 1.f : 0.f;
        const float zp1 = (v1 > THRv) ? 1.f : 0.f;
        const float zp2 = (v2 > THRv) ? 1.f : 0.f;
        const float zp3 = (v3 > THRv) ? 1.f : 0.f;

        v0 = __fsub_rn(__fadd_rn(__fmaf_rn(c_ALPHA, v0, tot0), xi.x), zp0);
        v1 = __fsub_rn(__fadd_rn(__fmaf_rn(c_ALPHA, v1, tot1), xi.y), zp1);
        v2 = __fsub_rn(__fadd_rn(__fmaf_rn(c_ALPHA, v2, tot2), xi.z), zp2);
        v3 = __fsub_rn(__fadd_rn(__fmaf_rn(c_ALPHA, v3, tot3), xi.w), zp3);

        const bool z0 = v0 > THRv, z1 = v1 > THRv, z2 = v2 > THRv, z3 = v3 > THRv;
        const int cnt = (int)z0 + (int)z1 + (int)z2 + (int)z3;

        // ---- ordered block scan -> ascending active list for t+1 ----
        int s = cnt;
#pragma unroll
        for (int o = 1; o < 32; o <<= 1) {
            int u = __shfl_up_sync(0xffffffffu, s, o);
            if (lane >= o) s += u;
        }
        if (lane == 31) s_wsum[wid] = s;
        __syncthreads();
        if (wid == 0 && lane < 8) {
            int u = s_wsum[lane];
            int sc = u;
#pragma unroll
            for (int o = 1; o < 8; o <<= 1) {
                int q = __shfl_up_sync(0xffu, sc, o);
                if (lane >= o) sc += q;
            }
            s_woff[lane] = sc - u;
            if (lane == 7) s_total = sc;
        }
        __syncthreads();

        int o = s_woff[wid] + s - cnt;
        if (z0) nxt[o++] = h4 + 0;
        if (z1) nxt[o++] = h4 + 1;
        if (z2) nxt[o++] = h4 + 2;
        if (z3) nxt[o++] = h4 + 3;

        const int incl = s_woff[wid] + s;
        if (tid == 79)  s_po[1] = incl;       // h < 320
        if (tid == 159) s_po[2] = incl;       // h < 640
        if (tid == 239) s_po[3] = incl;       // h < 960
        if (tid == 255) { s_po[4] = incl; s_po[0] = 0; }
        __syncthreads();

        // ---- output projection over new spikes (order-free) ----
        const int total = s_total;
        if (tid < OO * 8) {
            const int oo = tid >> 3, c = tid & 7;
            const float* wr = w_out + (size_t)oo * HH;
            float acc = 0.f;
            for (int i = c; i < total; i += 8)
                acc += wr[nxt[i]];
            s_red[oo][c] = acc;
        }
        __syncthreads();
        if (tid < OO) {
            float ssum = s_red[tid][0];
#pragma unroll
            for (int c = 1; c < 8; c++) ssum += s_red[tid][c];
            vo = __fmaf_rn(c_KAPPA, vo, ssum);
            out[((size_t)(t + 1) * BSZ + b) * OO + tid] = vo;
        }
        __syncthreads();
    }

    // ---- softmax of this b's 128 rows (warp per row) ----
    __syncthreads();
    for (int r = wid; r < T_ALL; r += 8) {
        float* pr = out + ((size_t)r * BSZ + b) * OO;
        float vv = (lane < OO) ? pr[lane] : -INFINITY;
        float m = vv;
#pragma unroll
        for (int off = 16; off > 0; off >>= 1)
            m = fmaxf(m, __shfl_xor_sync(0xffffffff, m, off));
        float e = (lane < OO) ? expf(vv - m) : 0.f;
        float sm = e;
#pragma unroll
        for (int off = 16; off > 0; off >>= 1)
            sm += __shfl_xor_sync(0xffffffff, sm, off);
        if (lane < OO) pr[lane] = e / sm;
    }
}

// ============================================================
extern "C" void kernel_launch(void* const* d_in, const int* in_sizes, int n_in,
                              void* d_out, int out_size) {
    const float* x     = (const float*)d_in[0];  // [128,256,512]
    const float* w_in  = (const float*)d_in[1];  // [1024,512]
    const float* w_rec = (const float*)d_in[2];  // [1024,1024]
    const float* w_out = (const float*)d_in[3];  // [20,1024]
    float* out = (float*)d_out;                  // [128,256,20]

    prep_k<<<512, 256>>>(w_rec);
    in_gemm<<<dim3(HH / 64, (T_STEPS * BSZ) / 128), 256>>>(x, w_in);
    step_all<<<BSZ, 256>>>(w_out, out);
}

// round 12
// speedup vs baseline: 1.3113x; 1.2483x over previous
#include <cuda_runtime.h>
#include <math.h>

#define T_ALL 128
#define T_STEPS 127
#define BSZ 256
#define DD 512
#define HH 1024
#define OO 20
#define KC 320                     // Eigen gebp kc panel boundary (confirmed R5)

__device__ __constant__ float c_ALPHA = 0.95122942450071400909f; // fp32(exp(-1/20))
__device__ __constant__ float c_KAPPA = 0.95122942450071400909f;
#define THRv 1.0f

// ---- scratch (device globals; no allocation allowed) ----
__device__ float g_xin[(size_t)T_STEPS * BSZ * HH];   // 133 MB
__device__ float g_WT[HH * HH];        // WT[j][h] = w_rec_eff[h][j] (diag zeroed)

// packed dual fp32 FMA (per-lane IEEE rn — bit-exact per chain)
#define FMA2(d_, a_, b_) \
    asm("fma.rn.f32x2 %0, %1, %2, %3;" : "=l"(d_) : "l"(a_), "l"(b_), "l"(d_))
#define PACK2(d_, x_) \
    asm("mov.b64 %0, {%1, %1};" : "=l"(d_) : "f"(x_))

__device__ __forceinline__ float2 unpack2(unsigned long long u) {
    float2 f;
    asm("mov.b64 {%0, %1}, %2;" : "=f"(f.x), "=f"(f.y) : "l"(u));
    return f;
}

// ============================================================
// prep: transposed, diagonal-zeroed recurrent weights
// ============================================================
__global__ void __launch_bounds__(256) prep_k(const float* __restrict__ w_rec) {
    int idx = blockIdx.x * 256 + threadIdx.x;
    int stride = gridDim.x * 256;
    for (int i = idx; i < HH * HH; i += stride) {
        int j = i / HH, h = i % HH;
        g_WT[i] = (h == j) ? 0.0f : w_rec[(size_t)h * HH + j];
    }
}

// ============================================================
// input GEMM (bit-exact ascending-k chain, kc=320 fold):
// 128m x 128n tile, BK=8 double-buffered, 256 threads, 8x8 microtile
// split 4+4 (lo / +64 hi) -> all LDS conflict-free.
// B natural (consecutive n = FMA2 pairs); A splatted via mov.b64.
// Per d: 4 LDS.128 + 8 MOV + 32 FMA2 for 64 MACs.
// grid (8, 254)
// ============================================================
__global__ void __launch_bounds__(256) in_gemm(const float* __restrict__ x,
                                               const float* __restrict__ w_in) {
    __shared__ float As[2][8][128];     // [k][m] natural
    __shared__ float Bs[2][8][128];     // [k][n] natural
    const int tid = threadIdx.x;
    const int m0 = blockIdx.y * 128;
    const int n0 = blockIdx.x * 128;

    const int lr = tid >> 1;            // 0..127 (row within tile)
    const int lk = (tid & 1) * 4;       // 0 or 4 (k quad)
    const int tm = (tid >> 4) * 4;      // 0..60  (m lo; hi = +64)
    const int tn = (tid & 15) * 4;      // 0..60  (n lo; hi = +64)

    const float* Ap = x + (size_t)(m0 + lr) * DD + lk;
    const float* Bp = w_in + (size_t)(n0 + lr) * DD + lk;

    float4 a  = __ldcs((const float4*)Ap);
    float4 bb = *(const float4*)Bp;
    As[0][lk + 0][lr] = a.x;  As[0][lk + 1][lr] = a.y;
    As[0][lk + 2][lr] = a.z;  As[0][lk + 3][lr] = a.w;
    Bs[0][lk + 0][lr] = bb.x; Bs[0][lk + 1][lr] = bb.y;
    Bs[0][lk + 2][lr] = bb.z; Bs[0][lk + 3][lr] = bb.w;
    __syncthreads();

    // acc2[i][jp]: m row i (0-3 lo, 4-7 hi=+64); jp: n pairs
    //   jp0=(tn,tn+1) jp1=(tn+2,tn+3) jp2=(tn+64,tn+65) jp3=(tn+66,tn+67)
    unsigned long long acc2[8][4];
#pragma unroll
    for (int i = 0; i < 8; i++)
#pragma unroll
        for (int j = 0; j < 4; j++) acc2[i][j] = 0ULL;

    int s = 0;
    for (int k0 = 0; k0 < DD; k0 += 8) {
        const int nk = k0 + 8;
        if (nk < DD) {                  // prefetch next k-tile
            a  = __ldcs((const float4*)(Ap + nk));
            bb = *(const float4*)(Bp + nk);
        }
#pragma unroll
        for (int d = 0; d < 8; d++) {   // ascending k
            float4 alo = *(const float4*)(&As[s][d][tm]);        // broadcast-class
            float4 ahi = *(const float4*)(&As[s][d][tm + 64]);
            ulonglong2 bl = *(const ulonglong2*)(&Bs[s][d][tn]);        // 16B stride: clean
            ulonglong2 bh = *(const ulonglong2*)(&Bs[s][d][tn + 64]);
            unsigned long long aa[8], bv[4] = {bl.x, bl.y, bh.x, bh.y};
            PACK2(aa[0], alo.x); PACK2(aa[1], alo.y);
            PACK2(aa[2], alo.z); PACK2(aa[3], alo.w);
            PACK2(aa[4], ahi.x); PACK2(aa[5], ahi.y);
            PACK2(aa[6], ahi.z); PACK2(aa[7], ahi.w);
#pragma unroll
            for (int i = 0; i < 8; i++)
#pragma unroll
                for (int j = 0; j < 4; j++)
                    FMA2(acc2[i][j], aa[i], bv[j]);
        }
        if (nk == KC) {                 // stage panel 0 to global, restart chain
#pragma unroll
            for (int i = 0; i < 8; i++) {
                const int mr = m0 + tm + (i & 3) + ((i >> 2) << 6);
                float2 u0 = unpack2(acc2[i][0]), u1 = unpack2(acc2[i][1]);
                float2 u2 = unpack2(acc2[i][2]), u3 = unpack2(acc2[i][3]);
                float* dst = g_xin + (size_t)mr * HH + n0 + tn;
                *(float4*)dst        = make_float4(u0.x, u0.y, u1.x, u1.y);
                *(float4*)(dst + 64) = make_float4(u2.x, u2.y, u3.x, u3.y);
#pragma unroll
                for (int j = 0; j < 4; j++) acc2[i][j] = 0ULL;
            }
        }
        if (nk < DD) {
            As[s ^ 1][lk + 0][lr] = a.x;  As[s ^ 1][lk + 1][lr] = a.y;
            As[s ^ 1][lk + 2][lr] = a.z;  As[s ^ 1][lk + 3][lr] = a.w;
            Bs[s ^ 1][lk + 0][lr] = bb.x; Bs[s ^ 1][lk + 1][lr] = bb.y;
            Bs[s ^ 1][lk + 2][lr] = bb.z; Bs[s ^ 1][lk + 3][lr] = bb.w;
        }
        __syncthreads();
        s ^= 1;
    }

    // fold: xin = fadd(p0, p1)  (exact Eigen panel fold)
#pragma unroll
    for (int i = 0; i < 8; i++) {
        const int mr = m0 + tm + (i & 3) + ((i >> 2) << 6);
        float* dst = g_xin + (size_t)mr * HH + n0 + tn;
        float4 p0 = *(const float4*)dst;
        float4 p1 = *(const float4*)(dst + 64);
        float2 u0 = unpack2(acc2[i][0]), u1 = unpack2(acc2[i][1]);
        float2 u2 = unpack2(acc2[i][2]), u3 = unpack2(acc2[i][3]);
        float4 o0, o1;
        o0.x = __fadd_rn(p0.x, u0.x); o0.y = __fadd_rn(p0.y, u0.y);
        o0.z = __fadd_rn(p0.z, u1.x); o0.w = __fadd_rn(p0.w, u1.y);
        o1.x = __fadd_rn(p1.x, u2.x); o1.y = __fadd_rn(p1.y, u2.y);
        o1.z = __fadd_rn(p1.z, u3.x); o1.w = __fadd_rn(p1.w, u3.y);
        __stcs((float4*)dst, o0);
        __stcs((float4*)(dst + 64), o1);
    }
}

// ============================================================
// persistent per-batch-row kernel: block b runs ALL 127 steps,
// then softmaxes its 128 output rows. Bit-exact v-path.
// ============================================================
__global__ void __launch_bounds__(256) step_all(const float* __restrict__ w_out,
                                                float* __restrict__ out) {
    const int b = blockIdx.x;
    const int tid = threadIdx.x;
    const int lane = tid & 31, wid = tid >> 5;
    const int h4 = tid * 4;

    __shared__ int lists[2][HH];
    __shared__ int s_po[5];
    __shared__ int s_wsum[8], s_woff[8];
    __shared__ int s_total;
    __shared__ float s_red[OO][9];

    float v0 = 0.f, v1 = 0.f, v2 = 0.f, v3 = 0.f;
    float vo = 0.f;

    if (tid < 5) s_po[tid] = 0;
    if (tid < OO) out[(size_t)b * OO + tid] = 0.f;   // row t=0
    __syncthreads();

    for (int t = 0; t < T_STEPS; t++) {
        const int* act = lists[t & 1];
        int* nxt = lists[(t + 1) & 1];

        // ---- sparse recurrent sum: exact per-panel chains, MLP-8 ----
        float tot0 = 0.f, tot1 = 0.f, tot2 = 0.f, tot3 = 0.f;
#pragma unroll 1
        for (int p = 0; p < 4; p++) {
            const int beg = s_po[p], end = s_po[p + 1];
            float a0 = 0.f, a1 = 0.f, a2 = 0.f, a3 = 0.f;
            int i = beg;
            for (; i + 8 <= end; i += 8) {
                float4 w[8];
#pragma unroll
                for (int q = 0; q < 8; q++)
                    w[q] = *(const float4*)(g_WT + (size_t)act[i + q] * HH + h4);
#pragma unroll
                for (int q = 0; q < 8; q++) {
                    a0 = __fadd_rn(a0, w[q].x);
                    a1 = __fadd_rn(a1, w[q].y);
                    a2 = __fadd_rn(a2, w[q].z);
                    a3 = __fadd_rn(a3, w[q].w);
                }
            }
            for (; i < end; i++) {
                const float4 w = *(const float4*)(g_WT + (size_t)act[i] * HH + h4);
                a0 = __fadd_rn(a0, w.x);
                a1 = __fadd_rn(a1, w.y);
                a2 = __fadd_rn(a2, w.z);
                a3 = __fadd_rn(a3, w.w);
            }
            tot0 = __fadd_rn(tot0, a0);
            tot1 = __fadd_rn(tot1, a1);
            tot2 = __fadd_rn(tot2, a2);
            tot3 = __fadd_rn(tot3, a3);
        }

        // ---- v update ----
        const float4 xi = __ldcs((const float4*)(g_xin + (size_t)t * BSZ * HH
                                                 + (size_t)b * HH + h4));
        const float zp0 = (v0 > THRv) ? 1.f : 0.f;
        const float zp1 = (v1 > THRv) ? 1.f : 0.f;
        const float zp2 = (v2 > THRv) ? 1.f : 0.f;
        const float zp3 = (v3 > THRv) ? 1.f : 0.f;

        v0 = __fsub_rn(__fadd_rn(__fmaf_rn(c_ALPHA, v0, tot0), xi.x), zp0);
        v1 = __fsub_rn(__fadd_rn(__fmaf_rn(c_ALPHA, v1, tot1), xi.y), zp1);
        v2 = __fsub_rn(__fadd_rn(__fmaf_rn(c_ALPHA, v2, tot2), xi.z), zp2);
        v3 = __fsub_rn(__fadd_rn(__fmaf_rn(c_ALPHA, v3, tot3), xi.w), zp3);

        const bool z0 = v0 > THRv, z1 = v1 > THRv, z2 = v2 > THRv, z3 = v3 > THRv;
        const int cnt = (int)z0 + (int)z1 + (int)z2 + (int)z3;

        // ---- ordered block scan -> ascending active list for t+1 ----
        int s = cnt;
#pragma unroll
        for (int o = 1; o < 32; o <<= 1) {
            int u = __shfl_up_sync(0xffffffffu, s, o);
            if (lane >= o) s += u;
        }
        if (lane == 31) s_wsum[wid] = s;
        __syncthreads();
        if (wid == 0 && lane < 8) {
            int u = s_wsum[lane];
            int sc = u;
#pragma unroll
            for (int o = 1; o < 8; o <<= 1) {
                int q = __shfl_up_sync(0xffu, sc, o);
                if (lane >= o) sc += q;
            }
            s_woff[lane] = sc - u;
            if (lane == 7) s_total = sc;
        }
        __syncthreads();

        int o = s_woff[wid] + s - cnt;
        if (z0) nxt[o++] = h4 + 0;
        if (z1) nxt[o++] = h4 + 1;
        if (z2) nxt[o++] = h4 + 2;
        if (z3) nxt[o++] = h4 + 3;

        const int incl = s_woff[wid] + s;
        if (tid == 79)  s_po[1] = incl;       // h < 320
        if (tid == 159) s_po[2] = incl;       // h < 640
        if (tid == 239) s_po[3] = incl;       // h < 960
        if (tid == 255) { s_po[4] = incl; s_po[0] = 0; }
        __syncthreads();

        // ---- output projection over new spikes (order-free) ----
        const int total = s_total;
        if (tid < OO * 8) {
            const int oo = tid >> 3, c = tid & 7;
            const float* wr = w_out + (size_t)oo * HH;
            float acc = 0.f;
            for (int i = c; i < total; i += 8)
                acc += wr[nxt[i]];
            s_red[oo][c] = acc;
        }
        __syncthreads();
        if (tid < OO) {
            float ssum = s_red[tid][0];
#pragma unroll
            for (int c = 1; c < 8; c++) ssum += s_red[tid][c];
            vo = __fmaf_rn(c_KAPPA, vo, ssum);
            out[((size_t)(t + 1) * BSZ + b) * OO + tid] = vo;
        }
        __syncthreads();
    }

    // ---- softmax of this b's 128 rows (warp per row) ----
    __syncthreads();
    for (int r = wid; r < T_ALL; r += 8) {
        float* pr = out + ((size_t)r * BSZ + b) * OO;
        float vv = (lane < OO) ? pr[lane] : -INFINITY;
        float m = vv;
#pragma unroll
        for (int off = 16; off > 0; off >>= 1)
            m = fmaxf(m, __shfl_xor_sync(0xffffffff, m, off));
        float e = (lane < OO) ? expf(vv - m) : 0.f;
        float sm = e;
#pragma unroll
        for (int off = 16; off > 0; off >>= 1)
            sm += __shfl_xor_sync(0xffffffff, sm, off);
        if (lane < OO) pr[lane] = e / sm;
    }
}

// ============================================================
extern "C" void kernel_launch(void* const* d_in, const int* in_sizes, int n_in,
                              void* d_out, int out_size) {
    const float* x     = (const float*)d_in[0];  // [128,256,512]
    const float* w_in  = (const float*)d_in[1];  // [1024,512]
    const float* w_rec = (const float*)d_in[2];  // [1024,1024]
    const float* w_out = (const float*)d_in[3];  // [20,1024]
    float* out = (float*)d_out;                  // [128,256,20]

    prep_k<<<512, 256>>>(w_rec);
    in_gemm<<<dim3(HH / 128, (T_STEPS * BSZ) / 128), 256>>>(x, w_in);
    step_all<<<BSZ, 256>>>(w_out, out);
}